// round 3
// baseline (speedup 1.0000x reference)
#include <cuda_runtime.h>

#define SC   25     // (LMAX+1)^2
#define RBC  12
#define RAC  11
#define DC   64
#define NP   15     // (l, m>=0) pairs
#define TPB  128

typedef unsigned long long u64;

// ---------- packed f32x2 helpers ----------
__device__ __forceinline__ u64 pk(float lo, float hi) {
    u64 r; asm("mov.b64 %0, {%1,%2};" : "=l"(r) : "f"(lo), "f"(hi)); return r;
}
__device__ __forceinline__ void unpk(u64 v, float& lo, float& hi) {
    asm("mov.b64 {%0,%1}, %2;" : "=f"(lo), "=f"(hi) : "l"(v));
}
__device__ __forceinline__ u64 fma2(u64 a, u64 b, u64 c) {
    u64 d; asm("fma.rn.f32x2 %0, %1, %2, %3;" : "=l"(d) : "l"(a), "l"(b), "l"(c)); return d;
}

// (l,m) pair tables, p = l(l+1)/2 + m, m = 0..l  (compile-time folded in unrolled loops)
static __device__ const int c_ip[NP] = {0, 2,3, 6,7,8, 12,13,14,15, 20,21,22,23,24};
static __device__ const int c_in[NP] = {0, 2,1, 6,5,4, 12,11,10, 9, 20,19,18,17,16};
static __device__ const int c_m [NP] = {0, 0,1, 0,1,2,  0, 1, 2, 3,  0, 1, 2, 3, 4};

#define XROW 36   // staging row stride in floats (32 data + 4 pad)

__global__ void __launch_bounds__(TPB, 4)
gtp_main(const float* __restrict__ x1, const float* __restrict__ x2,
         const float* __restrict__ W1, const float* __restrict__ W2,
         const float* __restrict__ Y,  const float* __restrict__ Yw,
         float* __restrict__ out, int nrows)
{
    __shared__ __align__(16) ulonglong2 sW[DC * 16];   // {W1(+m,-m) pair, W2 pair}, 16KB
    __shared__ __align__(16) u64 sP [RBC * 16];        // (P,P), row pad at 15
    __shared__ __align__(16) u64 sPw[RBC * 16];        // (P*qw, P*qw)
    __shared__ __align__(16) u64 sAng[RAC * 6];        // m=0..4 pairs (sqrt2 cos, sqrt2 sin); [5]=pad
    __shared__ __align__(16) float sX[TPB * XROW];     // input staging / output staging (18.4KB)

    const int tid = threadIdx.x;
    const float SQ2  = 1.41421356237309505f;
    const float ISQ2 = 0.70710678118654752f;

    // ---- build tables from W / Y / Yw (exact extraction, no trig) ----
    for (int k = tid; k < DC * NP; k += TPB) {
        int d = k / NP, p = k % NP;
        int l = (p >= 10) ? 4 : (p >= 6) ? 3 : (p >= 3) ? 2 : (p >= 1) ? 1 : 0;
        int m = p - l * (l + 1) / 2;
        int ip = l * l + l + m, in_ = ip - 2 * m;
        ulonglong2 w;
        w.x = pk(W1[d * SC + ip], W1[d * SC + in_]);
        w.y = pk(W2[d * SC + ip], W2[d * SC + in_]);
        sW[d * 16 + p] = w;
    }
    for (int d = tid; d < DC; d += TPB) { ulonglong2 z; z.x = 0; z.y = 0; sW[d * 16 + 15] = z; }

    for (int t = tid; t < RBC * 16; t += TPB) {
        int b = t / 16, p = t % 16;
        if (p == 15) { sP[t] = 0ull; sPw[t] = 0ull; }
        else {
            int l = (p >= 10) ? 4 : (p >= 6) ? 3 : (p >= 3) ? 2 : (p >= 1) ? 1 : 0;
            int m = p - l * (l + 1) / 2;
            int ip = l * l + l + m;
            float y0 = Y[(b * RAC) * SC + ip];                 // a=0 column: ang=1 (m=0) or sqrt2 (m>0)
            float P  = (m > 0) ? y0 * ISQ2 : y0;
            float qw = Yw[(b * RAC) * SC] / Y[(b * RAC) * SC]; // Y[b,0,0] > 0 const over a
            sP [t] = pk(P, P);
            float pw = P * qw;
            sPw[t] = pk(pw, pw);
        }
    }

    for (int t = tid; t < RAC * 6; t += TPB) {
        int a = t / 6, m = t % 6;
        if (m == 5)      sAng[t] = 0ull;
        else if (m == 0) sAng[t] = pk(1.0f, 0.0f);
        else {
            const int b0 = RBC / 2;                            // mid Gauss node, P[m,m] != 0
            int ip = m * m + 2 * m, in_ = m * m;
            float den = Y[(b0 * RAC) * SC + ip];               // sqrt2 * P[m,m](x_b0)
            float ac2 = SQ2 * Y[(b0 * RAC + a) * SC + ip ] / den;
            float as2 = SQ2 * Y[(b0 * RAC + a) * SC + in_] / den;
            sAng[t] = pk(ac2, as2);
        }
    }

    // ---- projection with staged, coalesced input loads (d-quarters of 16) ----
    u64 c1p[NP], c2p[NP];
    #pragma unroll
    for (int p = 0; p < NP; p++) { c1p[p] = 0ull; c2p[p] = 0ull; }

    const long long rowsLeft = (long long)nrows - (long long)blockIdx.x * TPB;
    const long long base = (long long)blockIdx.x * TPB * DC;
    float4* sXv = (float4*)sX;

    #pragma unroll 1
    for (int q = 0; q < 4; q++) {
        __syncthreads();   // protect sX from previous consumers
        // coalesced load: 128 rows x 16 floats per input for this quarter
        #pragma unroll
        for (int i = 0; i < 4; i++) {
            int k = i * TPB + tid;          // 0..511
            int row = k >> 2, c4 = k & 3;   // 4 float4 per row per input
            long long rg = (row < rowsLeft) ? row : (rowsLeft - 1);
            long long g = base + rg * DC + q * 16 + c4 * 4;
            sXv[row * 9 + c4]     = *(const float4*)(x1 + g);
            sXv[row * 9 + 4 + c4] = *(const float4*)(x2 + g);
        }
        __syncthreads();
        // consume: this thread's row, 16 d values per input
        #pragma unroll
        for (int j = 0; j < 4; j++) {
            float4 A = sXv[tid * 9 + j];
            float4 B = sXv[tid * 9 + 4 + j];
            float av[4] = {A.x, A.y, A.z, A.w};
            float bv[4] = {B.x, B.y, B.z, B.w};
            #pragma unroll
            for (int w = 0; w < 4; w++) {
                int d = q * 16 + j * 4 + w;
                u64 xd1 = pk(av[w], av[w]);
                u64 xd2 = pk(bv[w], bv[w]);
                const ulonglong2* Wd = &sW[d * 16];
                #pragma unroll
                for (int p = 0; p < NP; p++) {
                    ulonglong2 W = Wd[p];
                    c1p[p] = fma2(xd1, W.x, c1p[p]);
                    c2p[p] = fma2(xd2, W.y, c2p[p]);
                }
            }
        }
    }

    // ---- sphere: per beta node, F -> grid product -> H -> back-project ----
    u64 accp[NP];
    #pragma unroll
    for (int p = 0; p < NP; p++) accp[p] = 0ull;

    #pragma unroll 1
    for (int b = 0; b < RBC; b++) {
        const ulonglong2* Pv  = (const ulonglong2*)&sP [b * 16];
        const ulonglong2* Pwv = (const ulonglong2*)&sPw[b * 16];

        u64 F1[5], F2[5];
        #pragma unroll
        for (int m = 0; m < 5; m++) { F1[m] = 0ull; F2[m] = 0ull; }
        #pragma unroll
        for (int pp = 0; pp < 8; pp++) {
            ulonglong2 P2 = Pv[pp];
            const int p0 = 2 * pp, p1 = 2 * pp + 1;
            F1[c_m[p0]] = fma2(c1p[p0], P2.x, F1[c_m[p0]]);
            F2[c_m[p0]] = fma2(c2p[p0], P2.x, F2[c_m[p0]]);
            if (p1 < NP) {
                F1[c_m[p1]] = fma2(c1p[p1], P2.y, F1[c_m[p1]]);
                F2[c_m[p1]] = fma2(c2p[p1], P2.y, F2[c_m[p1]]);
            }
        }

        u64 H[5];
        #pragma unroll
        for (int m = 0; m < 5; m++) H[m] = 0ull;

        #pragma unroll
        for (int a = 0; a < RAC; a++) {
            const ulonglong2* Av = (const ulonglong2*)&sAng[a * 6];
            ulonglong2 A0 = Av[0], A1 = Av[1], A2 = Av[2];
            u64 am0 = A0.x, am1 = A0.y, am2 = A1.x, am3 = A1.y, am4 = A2.x;

            u64 g1 = 0ull, g2 = 0ull;
            g1 = fma2(F1[0], am0, g1);  g2 = fma2(F2[0], am0, g2);
            g1 = fma2(F1[1], am1, g1);  g2 = fma2(F2[1], am1, g2);
            g1 = fma2(F1[2], am2, g1);  g2 = fma2(F2[2], am2, g2);
            g1 = fma2(F1[3], am3, g1);  g2 = fma2(F2[3], am3, g2);
            g1 = fma2(F1[4], am4, g1);  g2 = fma2(F2[4], am4, g2);

            float l1, h1, l2, h2;
            unpk(g1, l1, h1); unpk(g2, l2, h2);
            float hh = (l1 + h1) * (l2 + h2);
            u64 hd = pk(hh, hh);
            H[0] = fma2(hd, am0, H[0]);
            H[1] = fma2(hd, am1, H[1]);
            H[2] = fma2(hd, am2, H[2]);
            H[3] = fma2(hd, am3, H[3]);
            H[4] = fma2(hd, am4, H[4]);
        }

        #pragma unroll
        for (int pp = 0; pp < 8; pp++) {
            ulonglong2 Pw2 = Pwv[pp];
            const int p0 = 2 * pp, p1 = 2 * pp + 1;
            accp[p0] = fma2(H[c_m[p0]], Pw2.x, accp[p0]);
            if (p1 < NP) accp[p1] = fma2(H[c_m[p1]], Pw2.y, accp[p1]);
        }
    }

    // ---- output: stage in shared, then coalesced float4 stores ----
    __syncthreads();                       // all threads done with sX as input staging
    float* sOut = sX;
    #pragma unroll
    for (int p = 0; p < NP; p++) {
        float lo, hi; unpk(accp[p], lo, hi);
        sOut[tid * SC + c_ip[p]] = lo;
        if (c_m[p] > 0) sOut[tid * SC + c_in[p]] = hi;
    }
    __syncthreads();
    const float4* sOv = (const float4*)sOut;
    const long long obase4 = (long long)blockIdx.x * TPB * SC / 4;   // CTA tile: 800 float4
    const long long otot4  = (long long)nrows * SC / 4;
    float4* og = (float4*)out;
    #pragma unroll
    for (int k = tid; k < TPB * SC / 4; k += TPB) {
        if (obase4 + k < otot4) og[obase4 + k] = sOv[k];
    }
}

extern "C" void kernel_launch(void* const* d_in, const int* in_sizes, int n_in,
                              void* d_out, int out_size) {
    const float* x1 = (const float*)d_in[0];
    const float* x2 = (const float*)d_in[1];
    const float* W1 = (const float*)d_in[2];
    const float* W2 = (const float*)d_in[3];
    const float* Y  = (const float*)d_in[4];
    const float* Yw = (const float*)d_in[5];
    float* out = (float*)d_out;

    const int nrows = in_sizes[0] / DC;            // 131072
    const int grid  = (nrows + TPB - 1) / TPB;     // 1024

    gtp_main<<<grid, TPB>>>(x1, x2, W1, W2, Y, Yw, out, nrows);
}

// round 4
// speedup vs baseline: 1.4153x; 1.4153x over previous
#include <cuda_runtime.h>

#define SC   25     // (LMAX+1)^2
#define RBC  12
#define RAC  11
#define DC   64
#define NP   15     // (l, m>=0) pairs
#define TPB  128

typedef unsigned long long u64;

// ---------- packed f32x2 helpers ----------
__device__ __forceinline__ u64 pk(float lo, float hi) {
    u64 r; asm("mov.b64 %0, {%1,%2};" : "=l"(r) : "f"(lo), "f"(hi)); return r;
}
__device__ __forceinline__ void unpk(u64 v, float& lo, float& hi) {
    asm("mov.b64 {%0,%1}, %2;" : "=f"(lo), "=f"(hi) : "l"(v));
}
__device__ __forceinline__ u64 fma2(u64 a, u64 b, u64 c) {
    u64 d; asm("fma.rn.f32x2 %0, %1, %2, %3;" : "=l"(d) : "l"(a), "l"(b), "l"(c)); return d;
}

// (l,m) pair tables, p = l(l+1)/2 + m, m = 0..l  (folded at compile time in unrolled loops)
static __device__ const int c_ip[NP] = {0, 2,3, 6,7,8, 12,13,14,15, 20,21,22,23,24};
static __device__ const int c_in[NP] = {0, 2,1, 6,5,4, 12,11,10, 9, 20,19,18,17,16};
static __device__ const int c_m [NP] = {0, 0,1, 0,1,2,  0, 1, 2, 3,  0, 1, 2, 3, 4};

__global__ void __launch_bounds__(TPB, 3)
gtp_main(const float* __restrict__ x1, const float* __restrict__ x2,
         const float* __restrict__ W1, const float* __restrict__ W2,
         const float* __restrict__ Y,  const float* __restrict__ Yw,
         float* __restrict__ out, int nrows)
{
    __shared__ __align__(16) ulonglong2 sW[DC * 16];  // {W1(+m,-m), W2(+m,-m)} pairs, 16KB
    __shared__ __align__(16) float4 sBuf[1024];       // input staging (x1|x2), later output staging; 16KB
    __shared__ __align__(16) u64 sP [RBC * 16];       // (P,P)
    __shared__ __align__(16) u64 sPw[RBC * 16];       // (P*qw, P*qw)
    __shared__ __align__(16) u64 sAng[6 * 6];         // alpha half-grid j=0..5: m=0..4 pairs + pad

    const int tid = threadIdx.x;
    const float SQ2  = 1.41421356237309505f;
    const float ISQ2 = 0.70710678118654752f;

    // ---- build tables from W / Y / Yw (exact extraction, no trig) ----
    for (int k = tid; k < DC * NP; k += TPB) {
        int d = k / NP, p = k % NP;
        int l = (p >= 10) ? 4 : (p >= 6) ? 3 : (p >= 3) ? 2 : (p >= 1) ? 1 : 0;
        int m = p - l * (l + 1) / 2;
        int ip = l * l + l + m, in_ = ip - 2 * m;
        ulonglong2 w;
        w.x = pk(W1[d * SC + ip], W1[d * SC + in_]);
        w.y = pk(W2[d * SC + ip], W2[d * SC + in_]);
        sW[d * 16 + p] = w;
    }
    for (int d = tid; d < DC; d += TPB) { ulonglong2 z; z.x = 0; z.y = 0; sW[d * 16 + 15] = z; }

    for (int t = tid; t < RBC * 16; t += TPB) {
        int b = t / 16, p = t % 16;
        if (p == 15) { sP[t] = 0ull; sPw[t] = 0ull; }
        else {
            int l = (p >= 10) ? 4 : (p >= 6) ? 3 : (p >= 3) ? 2 : (p >= 1) ? 1 : 0;
            int m = p - l * (l + 1) / 2;
            int ip = l * l + l + m;
            float y0 = Y[(b * RAC) * SC + ip];                 // a=0: ang=1 (m=0) or sqrt2 (m>0)
            float P  = (m > 0) ? y0 * ISQ2 : y0;
            float qw = Yw[(b * RAC) * SC] / Y[(b * RAC) * SC]; // Y[b,0,0] > 0, const over a
            sP [t] = pk(P, P);
            float pw = P * qw;
            sPw[t] = pk(pw, pw);
        }
    }

    // alpha half-grid: j=0..5 (points a=6..10 are mirrors of a=5..1)
    for (int t = tid; t < 6 * 6; t += TPB) {
        int a = t / 6, m = t % 6;
        if (m == 5)      sAng[t] = 0ull;
        else if (m == 0) sAng[t] = pk(1.0f, 0.0f);
        else {
            const int b0 = RBC / 2;                            // mid Gauss node, P[m,m] != 0
            int ip = m * m + 2 * m, in_ = m * m;
            float den = Y[(b0 * RAC) * SC + ip];               // sqrt2 * P[m,m](x_b0)
            float ac2 = SQ2 * Y[(b0 * RAC + a) * SC + ip ] / den;
            float as2 = SQ2 * Y[(b0 * RAC + a) * SC + in_] / den;
            sAng[t] = pk(ac2, as2);
        }
    }

    // ---- projection: staged coalesced loads, bank-swizzled staging ----
    u64 c1p[NP], c2p[NP];
    #pragma unroll
    for (int p = 0; p < NP; p++) { c1p[p] = 0ull; c2p[p] = 0ull; }

    const long long rowsLeft = (long long)nrows - (long long)blockIdx.x * TPB;
    const long long base = (long long)blockIdx.x * TPB * DC;

    #pragma unroll 1
    for (int q = 0; q < 4; q++) {
        __syncthreads();
        // coalesced: 128 rows x 16 floats per input for this d-quarter
        #pragma unroll
        for (int i = 0; i < 4; i++) {
            int k = i * TPB + tid;            // 0..511
            int row = k >> 2, c4 = k & 3;
            long long rg = (row < rowsLeft) ? row : (rowsLeft - 1);
            long long g = base + rg * DC + q * 16 + c4 * 4;
            int idx = c4 * 128 + ((row + 2 * c4) & 127);   // swizzle: conflict-free STS/LDS
            sBuf[idx]       = *(const float4*)(x1 + g);
            sBuf[512 + idx] = *(const float4*)(x2 + g);
        }
        __syncthreads();
        #pragma unroll
        for (int j = 0; j < 4; j++) {
            int idx = j * 128 + ((tid + 2 * j) & 127);
            float4 A = sBuf[idx];
            float4 B = sBuf[512 + idx];
            float av[4] = {A.x, A.y, A.z, A.w};
            float bv[4] = {B.x, B.y, B.z, B.w};
            #pragma unroll
            for (int w = 0; w < 4; w++) {
                int d = q * 16 + j * 4 + w;
                u64 xd1 = pk(av[w], av[w]);
                u64 xd2 = pk(bv[w], bv[w]);
                const ulonglong2* Wd = &sW[d * 16];
                #pragma unroll
                for (int p = 0; p < NP; p++) {
                    ulonglong2 W = Wd[p];
                    c1p[p] = fma2(xd1, W.x, c1p[p]);
                    c2p[p] = fma2(xd2, W.y, c2p[p]);
                }
            }
        }
    }

    // ---- sphere: per beta node, F -> mirrored alpha grid -> H -> back-project ----
    u64 accp[NP];
    #pragma unroll
    for (int p = 0; p < NP; p++) accp[p] = 0ull;

    #pragma unroll 1
    for (int b = 0; b < RBC; b++) {
        const ulonglong2* Pv  = (const ulonglong2*)&sP [b * 16];
        const ulonglong2* Pwv = (const ulonglong2*)&sPw[b * 16];

        u64 F1[5], F2[5];
        #pragma unroll
        for (int m = 0; m < 5; m++) { F1[m] = 0ull; F2[m] = 0ull; }
        #pragma unroll
        for (int pp = 0; pp < 8; pp++) {
            ulonglong2 P2 = Pv[pp];
            const int p0 = 2 * pp, p1 = 2 * pp + 1;
            F1[c_m[p0]] = fma2(c1p[p0], P2.x, F1[c_m[p0]]);
            F2[c_m[p0]] = fma2(c2p[p0], P2.x, F2[c_m[p0]]);
            if (p1 < NP) {
                F1[c_m[p1]] = fma2(c1p[p1], P2.y, F1[c_m[p1]]);
                F2[c_m[p1]] = fma2(c2p[p1], P2.y, F2[c_m[p1]]);
            }
        }

        u64 H[5];
        #pragma unroll
        for (int m = 0; m < 5; m++) H[m] = 0ull;

        // alpha half-grid: chain lanes = (cos-part, sin-part); g(a)=lo+hi, g(11-a)=lo-hi
        #pragma unroll
        for (int j = 0; j < 6; j++) {
            const ulonglong2* Av = (const ulonglong2*)&sAng[j * 6];
            ulonglong2 A0 = Av[0], A1 = Av[1], A2 = Av[2];
            u64 am0 = A0.x, am1 = A0.y, am2 = A1.x, am3 = A1.y, am4 = A2.x;

            u64 g1 = 0ull, g2 = 0ull;
            g1 = fma2(F1[0], am0, g1);  g2 = fma2(F2[0], am0, g2);
            g1 = fma2(F1[1], am1, g1);  g2 = fma2(F2[1], am1, g2);
            g1 = fma2(F1[2], am2, g1);  g2 = fma2(F2[2], am2, g2);
            g1 = fma2(F1[3], am3, g1);  g2 = fma2(F2[3], am3, g2);
            g1 = fma2(F1[4], am4, g1);  g2 = fma2(F2[4], am4, g2);

            float l1, h1, l2, h2;
            unpk(g1, l1, h1); unpk(g2, l2, h2);

            u64 hp;
            if (j == 0) {
                float ha = (l1 + h1) * (l2 + h2);          // a = 0 (self-mirror; sin lane = 0)
                hp = pk(ha, ha);
            } else {
                float ha = (l1 + h1) * (l2 + h2);          // point a = j
                float hb = (l1 - h1) * (l2 - h2);          // point a = 11 - j
                hp = pk(ha + hb, ha - hb);                 // (sum -> cos lane, diff -> sin lane)
            }
            H[0] = fma2(hp, am0, H[0]);
            H[1] = fma2(hp, am1, H[1]);
            H[2] = fma2(hp, am2, H[2]);
            H[3] = fma2(hp, am3, H[3]);
            H[4] = fma2(hp, am4, H[4]);
        }

        #pragma unroll
        for (int pp = 0; pp < 8; pp++) {
            ulonglong2 Pw2 = Pwv[pp];
            const int p0 = 2 * pp, p1 = 2 * pp + 1;
            accp[p0] = fma2(H[c_m[p0]], Pw2.x, accp[p0]);
            if (p1 < NP) accp[p1] = fma2(H[c_m[p1]], Pw2.y, accp[p1]);
        }
    }

    // ---- output: stage in shared (reuse sBuf), then coalesced float4 stores ----
    __syncthreads();                      // sBuf dead as input staging everywhere in CTA
    float* sOut = (float*)sBuf;
    #pragma unroll
    for (int p = 0; p < NP; p++) {
        float lo, hi; unpk(accp[p], lo, hi);
        sOut[tid * SC + c_ip[p]] = lo;
        if (c_m[p] > 0) sOut[tid * SC + c_in[p]] = hi;
    }
    __syncthreads();
    const float4* sOv = (const float4*)sOut;
    const long long obase4 = (long long)blockIdx.x * TPB * SC / 4;   // CTA tile: 800 float4
    const long long otot4  = (long long)nrows * SC / 4;
    float4* og = (float4*)out;
    #pragma unroll
    for (int k = tid; k < TPB * SC / 4; k += TPB) {
        if (obase4 + k < otot4) og[obase4 + k] = sOv[k];
    }
}

extern "C" void kernel_launch(void* const* d_in, const int* in_sizes, int n_in,
                              void* d_out, int out_size) {
    const float* x1 = (const float*)d_in[0];
    const float* x2 = (const float*)d_in[1];
    const float* W1 = (const float*)d_in[2];
    const float* W2 = (const float*)d_in[3];
    const float* Y  = (const float*)d_in[4];
    const float* Yw = (const float*)d_in[5];
    float* out = (float*)d_out;

    const int nrows = in_sizes[0] / DC;            // 131072
    const int grid  = (nrows + TPB - 1) / TPB;     // 1024

    gtp_main<<<grid, TPB>>>(x1, x2, W1, W2, Y, Yw, out, nrows);
}